// round 1
// baseline (speedup 1.0000x reference)
#include <cuda_runtime.h>
#include <math.h>

#define N_TOK 4096
#define D_MOD 512

// scratch (static device globals — no allocation allowed)
__device__ float g_Q[N_TOK * D_MOD];
__device__ float g_K[N_TOK * D_MOD];
__device__ float g_V[N_TOK * D_MOD];
__device__ float g_sigma[N_TOK];

// ---------------------------------------------------------------------------
// Tiled FP32 GEMM: C[M,N] = alpha * A[M,K] * op(B)
//   BT=true : B is [N,K] row-major (C = A * B^T)
//   BT=false: B is [K,N] row-major (C = A * B)
// BM=BN=128, BK=16, 256 threads, 8x8 per thread (quadrant mapping)
// ---------------------------------------------------------------------------
template <bool BT>
__global__ void __launch_bounds__(256) gemm128(
    const float* __restrict__ A, const float* __restrict__ B,
    float* __restrict__ C, int M, int N, int K, float alpha)
{
    constexpr int BM = 128, BN = 128, BK = 16;
    __shared__ float As[BK][BM];
    __shared__ float Bs[BK][BN];

    const int t  = threadIdx.x;
    const int tx = t & 15;    // 0..15  -> columns
    const int ty = t >> 4;    // 0..15  -> rows
    const int row0 = blockIdx.y * BM;
    const int col0 = blockIdx.x * BN;

    float acc[8][8];
#pragma unroll
    for (int i = 0; i < 8; i++)
#pragma unroll
        for (int j = 0; j < 8; j++) acc[i][j] = 0.f;

    for (int k0 = 0; k0 < K; k0 += BK) {
        // ---- load A tile (128 x 16), K-contiguous float4, store transposed
#pragma unroll
        for (int i = 0; i < 2; i++) {
            int l  = t + i * 256;
            int r  = l >> 2;
            int kq = (l & 3) * 4;
            float4 v = *(const float4*)&A[(size_t)(row0 + r) * K + k0 + kq];
            As[kq + 0][r] = v.x; As[kq + 1][r] = v.y;
            As[kq + 2][r] = v.z; As[kq + 3][r] = v.w;
        }
        // ---- load B tile
        if (BT) {
#pragma unroll
            for (int i = 0; i < 2; i++) {
                int l  = t + i * 256;
                int r  = l >> 2;
                int kq = (l & 3) * 4;
                float4 v = *(const float4*)&B[(size_t)(col0 + r) * K + k0 + kq];
                Bs[kq + 0][r] = v.x; Bs[kq + 1][r] = v.y;
                Bs[kq + 2][r] = v.z; Bs[kq + 3][r] = v.w;
            }
        } else {
#pragma unroll
            for (int i = 0; i < 2; i++) {
                int l  = t + i * 256;
                int kk = l >> 5;
                int nq = (l & 31) * 4;
                *(float4*)&Bs[kk][nq] =
                    *(const float4*)&B[(size_t)(k0 + kk) * N + col0 + nq];
            }
        }
        __syncthreads();

#pragma unroll
        for (int kk = 0; kk < BK; kk++) {
            float a[8], b[8];
            *(float4*)&a[0] = *(const float4*)&As[kk][ty * 4];
            *(float4*)&a[4] = *(const float4*)&As[kk][64 + ty * 4];
            *(float4*)&b[0] = *(const float4*)&Bs[kk][tx * 4];
            *(float4*)&b[4] = *(const float4*)&Bs[kk][64 + tx * 4];
#pragma unroll
            for (int i = 0; i < 8; i++)
#pragma unroll
                for (int j = 0; j < 8; j++)
                    acc[i][j] += a[i] * b[j];
        }
        __syncthreads();
    }

    // ---- epilogue: two float4 stores per row fragment
#pragma unroll
    for (int i = 0; i < 8; i++) {
        int r = row0 + ((i < 4) ? (ty * 4 + i) : (64 + ty * 4 + (i - 4)));
        float4 v0, v1;
        v0.x = alpha * acc[i][0]; v0.y = alpha * acc[i][1];
        v0.z = alpha * acc[i][2]; v0.w = alpha * acc[i][3];
        v1.x = alpha * acc[i][4]; v1.y = alpha * acc[i][5];
        v1.z = alpha * acc[i][6]; v1.w = alpha * acc[i][7];
        *(float4*)&C[(size_t)r * N + col0 + tx * 4]      = v0;
        *(float4*)&C[(size_t)r * N + col0 + 64 + tx * 4] = v1;
    }
}

// ---------------------------------------------------------------------------
// sigma[i] = clip(x[i,:] . Ws, 0.001, 1.0)  — one warp per row
// ---------------------------------------------------------------------------
__global__ void sigma_kernel(const float* __restrict__ x,
                             const float* __restrict__ Ws)
{
    int warp = (blockIdx.x * blockDim.x + threadIdx.x) >> 5;
    int lane = threadIdx.x & 31;
    if (warp >= N_TOK) return;
    float s = 0.f;
    for (int k = lane; k < D_MOD; k += 32)
        s += x[(size_t)warp * D_MOD + k] * Ws[k];
#pragma unroll
    for (int o = 16; o; o >>= 1) s += __shfl_xor_sync(0xffffffffu, s, o);
    if (lane == 0)
        g_sigma[warp] = fminf(fmaxf(s, 0.001f), 1.0f);
}

// ---------------------------------------------------------------------------
// P[i,:] = g / (sum(g) + 1e-8),  g_j = exp(-0.5((|i-j|)/sig)^2)/sqrt(2*pi*sig)
// one block (256 threads) per row
// ---------------------------------------------------------------------------
__global__ void p_kernel(float* __restrict__ P)
{
    __shared__ float buf[N_TOK];
    __shared__ float red[8];
    const int row = blockIdx.x;
    const int t = threadIdx.x;
    const float sg  = g_sigma[row];
    const float inv = 1.0f / sg;
    const float c   = rsqrtf(6.2831853071795864f * sg);

    float sum = 0.f;
    for (int j = t; j < N_TOK; j += 256) {
        float d = fabsf((float)(j - row));
        float u = d * inv;
        float g = c * __expf(-0.5f * u * u);
        buf[j] = g;
        sum += g;
    }
    // block reduce sum
    int lane = t & 31, w = t >> 5;
#pragma unroll
    for (int o = 16; o; o >>= 1) sum += __shfl_xor_sync(0xffffffffu, sum, o);
    if (lane == 0) red[w] = sum;
    __syncthreads();
    if (t == 0) {
        float s = 0.f;
#pragma unroll
        for (int i = 0; i < 8; i++) s += red[i];
        red[0] = s;
    }
    __syncthreads();
    const float scale = 1.0f / (red[0] + 1e-8f);

    for (int j = t; j < N_TOK; j += 256)
        P[(size_t)row * N_TOK + j] = buf[j] * scale;
}

// ---------------------------------------------------------------------------
// in-place row softmax on S (raw scores already scaled by 1/sqrt(d))
// one block (256 threads) per row
// ---------------------------------------------------------------------------
__global__ void softmax_kernel(float* __restrict__ S)
{
    __shared__ float buf[N_TOK];
    __shared__ float red[8];
    const int row = blockIdx.x;
    const int t = threadIdx.x;
    const int lane = t & 31, w = t >> 5;
    float* srow = S + (size_t)row * N_TOK;

    // pass 1: load + max
    float m = -INFINITY;
    for (int j = t; j < N_TOK; j += 256) {
        float v = srow[j];
        buf[j] = v;
        m = fmaxf(m, v);
    }
#pragma unroll
    for (int o = 16; o; o >>= 1) m = fmaxf(m, __shfl_xor_sync(0xffffffffu, m, o));
    if (lane == 0) red[w] = m;
    __syncthreads();
    if (t == 0) {
        float v = red[0];
#pragma unroll
        for (int i = 1; i < 8; i++) v = fmaxf(v, red[i]);
        red[0] = v;
    }
    __syncthreads();
    m = red[0];
    __syncthreads();

    // pass 2: exp + sum
    float sum = 0.f;
    for (int j = t; j < N_TOK; j += 256) {
        float e = __expf(buf[j] - m);
        buf[j] = e;
        sum += e;
    }
#pragma unroll
    for (int o = 16; o; o >>= 1) sum += __shfl_xor_sync(0xffffffffu, sum, o);
    if (lane == 0) red[w] = sum;
    __syncthreads();
    if (t == 0) {
        float s = 0.f;
#pragma unroll
        for (int i = 0; i < 8; i++) s += red[i];
        red[0] = s;
    }
    __syncthreads();
    const float scale = 1.0f / red[0];

    for (int j = t; j < N_TOK; j += 256)
        srow[j] = buf[j] * scale;
}

// ---------------------------------------------------------------------------
extern "C" void kernel_launch(void* const* d_in, const int* in_sizes, int n_in,
                              void* d_out, int out_size)
{
    const float* x  = (const float*)d_in[0];
    const float* Wq = (const float*)d_in[1];
    const float* Wk = (const float*)d_in[2];
    const float* Wv = (const float*)d_in[3];
    const float* Ws = (const float*)d_in[4];

    float* out = (float*)d_out;
    float* Z = out;                                   // [4096, 512]
    float* P = out + (size_t)N_TOK * D_MOD;           // [4096, 4096]
    float* S = P + (size_t)N_TOK * N_TOK;             // [4096, 4096]

    float *qp, *kp, *vp;
    cudaGetSymbolAddress((void**)&qp, g_Q);
    cudaGetSymbolAddress((void**)&kp, g_K);
    cudaGetSymbolAddress((void**)&vp, g_V);

    dim3 blk(256);

    // 1) Q, K, V = x @ W^T   (M=4096, N=512, K=512)
    dim3 gQKV(D_MOD / 128, N_TOK / 128);
    gemm128<true><<<gQKV, blk>>>(x, Wq, qp, N_TOK, D_MOD, D_MOD, 1.0f);
    gemm128<true><<<gQKV, blk>>>(x, Wk, kp, N_TOK, D_MOD, D_MOD, 1.0f);
    gemm128<true><<<gQKV, blk>>>(x, Wv, vp, N_TOK, D_MOD, D_MOD, 1.0f);

    // 2) sigma
    sigma_kernel<<<(N_TOK * 32 + 255) / 256, blk>>>(x, Ws);

    // 3) P (prior association)
    p_kernel<<<N_TOK, blk>>>(P);

    // 4) raw scores into S region: S = (Q K^T) / sqrt(d)
    dim3 gS(N_TOK / 128, N_TOK / 128);
    gemm128<true><<<gS, blk>>>(qp, kp, S, N_TOK, N_TOK, D_MOD,
                               1.0f / sqrtf((float)D_MOD));

    // 5) softmax rows of S in place
    softmax_kernel<<<N_TOK, blk>>>(S);

    // 6) Z = S @ V   (M=4096, N=512, K=4096)
    dim3 gZ(D_MOD / 128, N_TOK / 128);
    gemm128<false><<<gZ, blk>>>(S, vp, Z, N_TOK, D_MOD, N_TOK, 1.0f);
}

// round 2
// speedup vs baseline: 2.5491x; 2.5491x over previous
#include <cuda_runtime.h>
#include <math.h>
#include <stdint.h>

#define N_TOK 4096
#define D_MOD 512

// scratch (no allocation allowed)
__device__ float g_Q[N_TOK * D_MOD];
__device__ float g_K[N_TOK * D_MOD];
__device__ float g_V[N_TOK * D_MOD];
__device__ float g_sigma[N_TOK];

__device__ __forceinline__ uint32_t f2tf32(float x) {
    uint32_t u;
    asm("cvt.rna.tf32.f32 %0, %1;" : "=r"(u) : "f"(x));
    return u;
}

__device__ __forceinline__ void mma_tf32(float* d, const uint32_t* a, const uint32_t* b) {
    asm volatile(
        "mma.sync.aligned.m16n8k8.row.col.f32.tf32.tf32.f32 "
        "{%0,%1,%2,%3}, {%4,%5,%6,%7}, {%8,%9}, {%0,%1,%2,%3};"
        : "+f"(d[0]), "+f"(d[1]), "+f"(d[2]), "+f"(d[3])
        : "r"(a[0]), "r"(a[1]), "r"(a[2]), "r"(a[3]), "r"(b[0]), "r"(b[1]));
}

// ---------------------------------------------------------------------------
// Tensor-core GEMM core. C[M,N] = alpha * A[M,K] * op(B).
//   BT=true : B is [N,K] row-major (C = A*B^T)
//   BT=false: B is [K,N] row-major (C = A*B)
// BM=BN=128, BK=32, 256 threads (8 warps, 2x4), warp tile 64x32.
// ---------------------------------------------------------------------------
template <bool BT>
__device__ __forceinline__ void gemm_core(
    const float* __restrict__ A, const float* __restrict__ B,
    float* __restrict__ C, int N, int K, float alpha)
{
    constexpr int BM = 128, BN = 128, BK = 32;
    constexpr int LDA = BK + 4;                 // 36 words, conflict-free both paths
    constexpr int LDB2 = BN + 4;                // 132 (only for BT=false)

    __shared__ uint32_t As[BM * LDA];
    __shared__ uint32_t Bs[BT ? (BN * LDA) : (BK * LDB2)];

    const int t    = threadIdx.x;
    const int wid  = t >> 5;
    const int lane = t & 31;
    const int r    = lane >> 2;     // 0..7
    const int c    = lane & 3;      // 0..3
    const int warpM = (wid >> 2) * 64;   // 0 / 64
    const int warpN = (wid & 3) * 32;    // 0..96
    const int row0 = blockIdx.y * BM;
    const int col0 = blockIdx.x * BN;

    const int arow = t >> 3;            // 0..31 (+ i*32)
    const int akq  = (t & 7) << 2;      // 0..28

    float4 ra[4], rb[4];

    auto ldgA = [&](int k0) {
#pragma unroll
        for (int i = 0; i < 4; i++)
            ra[i] = *(const float4*)&A[(size_t)(row0 + arow + i * 32) * K + k0 + akq];
    };
    auto stsA = [&]() {
#pragma unroll
        for (int i = 0; i < 4; i++) {
            uint4 v;
            v.x = f2tf32(ra[i].x); v.y = f2tf32(ra[i].y);
            v.z = f2tf32(ra[i].z); v.w = f2tf32(ra[i].w);
            *(uint4*)&As[(arow + i * 32) * LDA + akq] = v;
        }
    };
    auto ldgB = [&](int k0) {
        if (BT) {
#pragma unroll
            for (int i = 0; i < 4; i++)
                rb[i] = *(const float4*)&B[(size_t)(col0 + arow + i * 32) * K + k0 + akq];
        } else {
#pragma unroll
            for (int i = 0; i < 4; i++) {
                int l = i * 256 + t;
                rb[i] = *(const float4*)&B[(size_t)(k0 + (l >> 5)) * N + col0 + ((l & 31) << 2)];
            }
        }
    };
    auto stsB = [&]() {
        if (BT) {
#pragma unroll
            for (int i = 0; i < 4; i++) {
                uint4 v;
                v.x = f2tf32(rb[i].x); v.y = f2tf32(rb[i].y);
                v.z = f2tf32(rb[i].z); v.w = f2tf32(rb[i].w);
                *(uint4*)&Bs[(arow + i * 32) * LDA + akq] = v;
            }
        } else {
#pragma unroll
            for (int i = 0; i < 4; i++) {
                int l = i * 256 + t;
                uint4 v;
                v.x = f2tf32(rb[i].x); v.y = f2tf32(rb[i].y);
                v.z = f2tf32(rb[i].z); v.w = f2tf32(rb[i].w);
                *(uint4*)&Bs[(l >> 5) * LDB2 + ((l & 31) << 2)] = v;
            }
        }
    };

    float acc[4][4][4] = {};

    auto compute = [&]() {
#pragma unroll
        for (int kk = 0; kk < BK; kk += 8) {
            uint32_t af[4][4], bf[4][2];
#pragma unroll
            for (int mi = 0; mi < 4; mi++) {
                const uint32_t* base = &As[(warpM + mi * 16 + r) * LDA + kk + c];
                af[mi][0] = base[0];
                af[mi][1] = base[8 * LDA];
                af[mi][2] = base[4];
                af[mi][3] = base[8 * LDA + 4];
            }
#pragma unroll
            for (int ni = 0; ni < 4; ni++) {
                if (BT) {
                    const uint32_t* base = &Bs[(warpN + ni * 8 + r) * LDA + kk + c];
                    bf[ni][0] = base[0];
                    bf[ni][1] = base[4];
                } else {
                    const uint32_t* base = &Bs[(kk + c) * LDB2 + warpN + ni * 8 + r];
                    bf[ni][0] = base[0];
                    bf[ni][1] = base[4 * LDB2];
                }
            }
#pragma unroll
            for (int mi = 0; mi < 4; mi++)
#pragma unroll
                for (int ni = 0; ni < 4; ni++)
                    mma_tf32(acc[mi][ni], af[mi], bf[ni]);
        }
    };

    ldgA(0); ldgB(0);
    stsA(); stsB();
    __syncthreads();
    for (int k0 = BK; k0 < K; k0 += BK) {
        ldgA(k0); ldgB(k0);     // overlap next-tile LDG with compute
        compute();
        __syncthreads();
        stsA(); stsB();
        __syncthreads();
    }
    compute();

#pragma unroll
    for (int mi = 0; mi < 4; mi++) {
        int row = row0 + warpM + mi * 16 + r;
#pragma unroll
        for (int ni = 0; ni < 4; ni++) {
            int col = col0 + warpN + ni * 8 + 2 * c;
            float2 v0 = make_float2(alpha * acc[mi][ni][0], alpha * acc[mi][ni][1]);
            float2 v1 = make_float2(alpha * acc[mi][ni][2], alpha * acc[mi][ni][3]);
            *(float2*)&C[(size_t)row * N + col]       = v0;
            *(float2*)&C[(size_t)(row + 8) * N + col] = v1;
        }
    }
}

// ---------------------------------------------------------------------------
__global__ void __launch_bounds__(256) qkv_kernel(
    const float* __restrict__ x, const float* __restrict__ Wq,
    const float* __restrict__ Wk, const float* __restrict__ Wv)
{
    const float* W = (blockIdx.z == 0) ? Wq : (blockIdx.z == 1) ? Wk : Wv;
    float* Cd = (blockIdx.z == 0) ? g_Q : (blockIdx.z == 1) ? g_K : g_V;
    gemm_core<true>(x, W, Cd, D_MOD, D_MOD, 1.0f);
}

__global__ void __launch_bounds__(256) s_gemm_kernel(float* __restrict__ S)
{
    gemm_core<true>(g_Q, g_K, S, N_TOK, D_MOD, 0.044194173824159216f); // 1/sqrt(512)
}

__global__ void __launch_bounds__(256) z_gemm_kernel(
    const float* __restrict__ S, float* __restrict__ Z)
{
    gemm_core<false>(S, g_V, Z, D_MOD, N_TOK, 1.0f);
}

// ---------------------------------------------------------------------------
// sigma[i] = clip(x[i,:].Ws, 0.001, 1.0) — one warp per row, float4 loads
// ---------------------------------------------------------------------------
__global__ void sigma_kernel(const float* __restrict__ x, const float* __restrict__ Ws)
{
    int row  = blockIdx.x * (blockDim.x >> 5) + (threadIdx.x >> 5);
    int lane = threadIdx.x & 31;
    if (row >= N_TOK) return;
    const float4* xr = (const float4*)(x + (size_t)row * D_MOD);
    const float4* w  = (const float4*)Ws;
    float s = 0.f;
#pragma unroll
    for (int k = lane; k < D_MOD / 4; k += 32) {
        float4 a = xr[k], b = w[k];
        s += a.x * b.x + a.y * b.y + a.z * b.z + a.w * b.w;
    }
#pragma unroll
    for (int o = 16; o; o >>= 1) s += __shfl_xor_sync(0xffffffffu, s, o);
    if (lane == 0) g_sigma[row] = fminf(fmaxf(s, 0.001f), 1.0f);
}

// ---------------------------------------------------------------------------
// P: sigma <= 1  =>  exp(-0.5 (d/sigma)^2) == 0 in fp32 for d >= 15.
// Zero-fill whole P, then compute only a +-32 band per row.
// ---------------------------------------------------------------------------
__global__ void zero_kernel(float4* __restrict__ p, int n4)
{
    int i = blockIdx.x * blockDim.x + threadIdx.x;
    if (i < n4) p[i] = make_float4(0.f, 0.f, 0.f, 0.f);
}

#define BAND 32

__global__ void p_band_kernel(float* __restrict__ P)
{
    int row  = blockIdx.x * (blockDim.x >> 5) + (threadIdx.x >> 5);
    int lane = threadIdx.x & 31;
    if (row >= N_TOK) return;

    const float sg  = g_sigma[row];
    const float inv = 1.0f / sg;
    const float cc  = rsqrtf(6.283185307179586f * sg);
    const int j0 = max(row - BAND, 0);
    const int j1 = min(row + BAND, N_TOK - 1);

    float sum = 0.f;
    for (int j = j0 + lane; j <= j1; j += 32) {
        float u = (float)(j - row) * inv;
        sum += cc * __expf(-0.5f * u * u);
    }
#pragma unroll
    for (int o = 16; o; o >>= 1) sum += __shfl_xor_sync(0xffffffffu, sum, o);
    const float scale = 1.0f / (sum + 1e-8f);

    for (int j = j0 + lane; j <= j1; j += 32) {
        float u = (float)(j - row) * inv;
        P[(size_t)row * N_TOK + j] = cc * __expf(-0.5f * u * u) * scale;
    }
}

// ---------------------------------------------------------------------------
// in-place row softmax, one block (256 thr) per row
// ---------------------------------------------------------------------------
__global__ void softmax_kernel(float* __restrict__ S)
{
    __shared__ float buf[N_TOK];
    __shared__ float red[8];
    const int row = blockIdx.x;
    const int t = threadIdx.x;
    const int lane = t & 31, w = t >> 5;
    float* srow = S + (size_t)row * N_TOK;

    float m = -INFINITY;
    for (int j = t; j < N_TOK; j += 256) {
        float v = srow[j];
        buf[j] = v;
        m = fmaxf(m, v);
    }
#pragma unroll
    for (int o = 16; o; o >>= 1) m = fmaxf(m, __shfl_xor_sync(0xffffffffu, m, o));
    if (lane == 0) red[w] = m;
    __syncthreads();
    if (t == 0) {
        float v = red[0];
#pragma unroll
        for (int i = 1; i < 8; i++) v = fmaxf(v, red[i]);
        red[0] = v;
    }
    __syncthreads();
    m = red[0];
    __syncthreads();

    float sum = 0.f;
    for (int j = t; j < N_TOK; j += 256) {
        float e = __expf(buf[j] - m);
        buf[j] = e;
        sum += e;
    }
#pragma unroll
    for (int o = 16; o; o >>= 1) sum += __shfl_xor_sync(0xffffffffu, sum, o);
    if (lane == 0) red[w] = sum;
    __syncthreads();
    if (t == 0) {
        float s = 0.f;
#pragma unroll
        for (int i = 0; i < 8; i++) s += red[i];
        red[0] = s;
    }
    __syncthreads();
    const float scale = 1.0f / red[0];

    for (int j = t; j < N_TOK; j += 256)
        srow[j] = buf[j] * scale;
}

// ---------------------------------------------------------------------------
extern "C" void kernel_launch(void* const* d_in, const int* in_sizes, int n_in,
                              void* d_out, int out_size)
{
    const float* x  = (const float*)d_in[0];
    const float* Wq = (const float*)d_in[1];
    const float* Wk = (const float*)d_in[2];
    const float* Wv = (const float*)d_in[3];
    const float* Ws = (const float*)d_in[4];

    float* out = (float*)d_out;
    float* Z = out;                          // [4096, 512]
    float* P = out + (size_t)N_TOK * D_MOD;  // [4096, 4096]
    float* S = P + (size_t)N_TOK * N_TOK;    // [4096, 4096]

    dim3 blk(256);

    // 1) Q,K,V = x @ W^T  (fused over z)
    dim3 gQKV(D_MOD / 128, N_TOK / 128, 3);
    qkv_kernel<<<gQKV, blk>>>(x, Wq, Wk, Wv);

    // 2) sigma
    sigma_kernel<<<N_TOK / 8, blk>>>(x, Ws);

    // 3) P = zero + Gaussian band
    int n4 = (N_TOK * N_TOK) / 4;
    zero_kernel<<<(n4 + 255) / 256, blk>>>((float4*)P, n4);
    p_band_kernel<<<N_TOK / 8, blk>>>(P);

    // 4) raw scores: S = (Q K^T)/sqrt(d)
    dim3 gS(N_TOK / 128, N_TOK / 128);
    s_gemm_kernel<<<gS, blk>>>(S);

    // 5) softmax rows in place
    softmax_kernel<<<N_TOK, blk>>>(S);

    // 6) Z = S @ V
    dim3 gZ(D_MOD / 128, N_TOK / 128);
    z_gemm_kernel<<<gZ, blk>>>(S, Z);
}

// round 4
// speedup vs baseline: 3.0713x; 1.2049x over previous
#include <cuda_runtime.h>
#include <math.h>
#include <stdint.h>

#define N_TOK 4096
#define D_MOD 512

// scratch (static device globals — no allocation allowed)
__device__ float g_X32[N_TOK * D_MOD];
__device__ float g_Wq32[D_MOD * D_MOD];
__device__ float g_Wk32[D_MOD * D_MOD];
__device__ float g_Wv32[D_MOD * D_MOD];
__device__ float g_Q32[N_TOK * D_MOD];
__device__ float g_K32[N_TOK * D_MOD];
__device__ float g_V32[N_TOK * D_MOD];
__device__ float g_S32[(size_t)N_TOK * N_TOK];
__device__ float g_sigma[N_TOK];

__device__ __forceinline__ uint32_t smem_u32(const void* p) {
    uint32_t a;
    asm("{ .reg .u64 t; cvta.to.shared.u64 t, %1; cvt.u32.u64 %0, t; }" : "=r"(a) : "l"(p));
    return a;
}
__device__ __forceinline__ uint32_t f2tf32(float x) {
    uint32_t u;
    asm("cvt.rna.tf32.f32 %0, %1;" : "=r"(u) : "f"(x));
    return u;
}
__device__ __forceinline__ void mma_tf32(float* d, const uint32_t* a, const uint32_t* b) {
    asm volatile(
        "mma.sync.aligned.m16n8k8.row.col.f32.tf32.tf32.f32 "
        "{%0,%1,%2,%3}, {%4,%5,%6,%7}, {%8,%9}, {%0,%1,%2,%3};"
        : "+f"(d[0]), "+f"(d[1]), "+f"(d[2]), "+f"(d[3])
        : "r"(a[0]), "r"(a[1]), "r"(a[2]), "r"(a[3]), "r"(b[0]), "r"(b[1]));
}
__device__ __forceinline__ void cp16(uint32_t s, const float* g) {
    asm volatile("cp.async.cg.shared.global [%0], [%1], 16;" :: "r"(s), "l"(g));
}

// ---------------------------------------------------------------------------
// cp.async 3-stage tf32 GEMM. Operands are PRE-ROUNDED tf32 bits in fp32 slots.
//   C[M,N] = alpha * A[M,K] * op(B)
//   BT=true : B is [N,K] row-major; BT=false: B is [K,N] row-major.
//   ROUND: store C as rna-rounded tf32 bit patterns (for scratch intermediates)
// BM=BN=128, BK=32, 256 threads (8 warps 2x4), warp tile 64x32.
// ---------------------------------------------------------------------------
#define STAGES 3
#define AWORDS (128 * 36)
#define BWORDS 4608
#define STAGE_WORDS (AWORDS + BWORDS)        // 9216 words = 36864 B
#define DYN_SMEM (STAGES * STAGE_WORDS * 4)  // 110592 B

template <bool BT, bool ROUND>
__device__ __forceinline__ void gemm_core(
    const float* __restrict__ A, const float* __restrict__ B,
    float* __restrict__ C, int K, int NC, float alpha)
{
    extern __shared__ float smem[];
    const uint32_t smem_base = smem_u32(smem);
    const int t    = threadIdx.x;
    const int wid  = t >> 5;
    const int lane = t & 31;
    const int r    = lane >> 2;
    const int c    = lane & 3;
    const int warpM = (wid >> 2) * 64;
    const int warpN = (wid & 3) * 32;
    const int row0 = blockIdx.y * 128;
    const int col0 = blockIdx.x * 128;
    const int iters = K >> 5;

    auto stage_load = [&](int sidx) {
        const int buf = sidx % STAGES;
        const int k0  = sidx << 5;
        const uint32_t abase = smem_base + (uint32_t)buf * (STAGE_WORDS * 4);
        const uint32_t bbase = abase + AWORDS * 4;
#pragma unroll
        for (int i = 0; i < 4; i++) {
            int l = i * 256 + t;
            int rr = l >> 3, cc = (l & 7) << 2;
            cp16(abase + (uint32_t)(rr * 36 + cc) * 4,
                 &A[(size_t)(row0 + rr) * K + k0 + cc]);
        }
        if (BT) {
#pragma unroll
            for (int i = 0; i < 4; i++) {
                int l = i * 256 + t;
                int rr = l >> 3, cc = (l & 7) << 2;
                cp16(bbase + (uint32_t)(rr * 36 + cc) * 4,
                     &B[(size_t)(col0 + rr) * K + k0 + cc]);
            }
        } else {
#pragma unroll
            for (int i = 0; i < 4; i++) {
                int l = i * 256 + t;
                int kk = l >> 5, nn = (l & 31) << 2;
                cp16(bbase + (uint32_t)(kk * 132 + nn) * 4,
                     &B[(size_t)(k0 + kk) * NC + col0 + nn]);
            }
        }
        asm volatile("cp.async.commit_group;" ::: "memory");
    };

    float acc[4][4][4] = {};

    stage_load(0);
    stage_load(1);

    for (int it = 0; it < iters; ++it) {
        const int buf = it % STAGES;
        asm volatile("cp.async.wait_group %0;" :: "n"(STAGES - 2) : "memory");
        __syncthreads();
        if (it + STAGES - 1 < iters) stage_load(it + STAGES - 1);

        const uint32_t* As32 = (const uint32_t*)(smem + buf * STAGE_WORDS);
        const uint32_t* Bs32 = As32 + AWORDS;

#pragma unroll
        for (int kk = 0; kk < 32; kk += 8) {
            uint32_t af[4][4], bf[4][2];
#pragma unroll
            for (int mi = 0; mi < 4; mi++) {
                const uint32_t* base = &As32[(warpM + mi * 16 + r) * 36 + kk + c];
                af[mi][0] = base[0];
                af[mi][1] = base[8 * 36];
                af[mi][2] = base[4];
                af[mi][3] = base[8 * 36 + 4];
            }
#pragma unroll
            for (int ni = 0; ni < 4; ni++) {
                if (BT) {
                    const uint32_t* base = &Bs32[(warpN + ni * 8 + r) * 36 + kk + c];
                    bf[ni][0] = base[0];
                    bf[ni][1] = base[4];
                } else {
                    const uint32_t* base = &Bs32[(kk + c) * 132 + warpN + ni * 8 + r];
                    bf[ni][0] = base[0];
                    bf[ni][1] = base[4 * 132];
                }
            }
#pragma unroll
            for (int mi = 0; mi < 4; mi++)
#pragma unroll
                for (int ni = 0; ni < 4; ni++)
                    mma_tf32(acc[mi][ni], af[mi], bf[ni]);
        }
    }

    // epilogue
#pragma unroll
    for (int mi = 0; mi < 4; mi++) {
        int row = row0 + warpM + mi * 16 + r;
#pragma unroll
        for (int ni = 0; ni < 4; ni++) {
            int col = col0 + warpN + ni * 8 + 2 * c;
            float o0 = alpha * acc[mi][ni][0], o1 = alpha * acc[mi][ni][1];
            float o2 = alpha * acc[mi][ni][2], o3 = alpha * acc[mi][ni][3];
            float2 v0, v1;
            if (ROUND) {
                v0 = make_float2(__uint_as_float(f2tf32(o0)), __uint_as_float(f2tf32(o1)));
                v1 = make_float2(__uint_as_float(f2tf32(o2)), __uint_as_float(f2tf32(o3)));
            } else {
                v0 = make_float2(o0, o1);
                v1 = make_float2(o2, o3);
            }
            *(float2*)&C[(size_t)row * NC + col]       = v0;
            *(float2*)&C[(size_t)(row + 8) * NC + col] = v1;
        }
    }
}

__global__ void __launch_bounds__(256) qkv_ca_kernel()
{
    if (blockIdx.z == 0)      gemm_core<true, true>(g_X32, g_Wq32, g_Q32, D_MOD, D_MOD, 1.0f);
    else if (blockIdx.z == 1) gemm_core<true, true>(g_X32, g_Wk32, g_K32, D_MOD, D_MOD, 1.0f);
    else                      gemm_core<true, true>(g_X32, g_Wv32, g_V32, D_MOD, D_MOD, 1.0f);
}

__global__ void __launch_bounds__(256) s_ca_kernel(float* __restrict__ S)
{
    gemm_core<true, false>(g_Q32, g_K32, S, D_MOD, N_TOK, 0.044194173824159216f); // 1/sqrt(512)
}

__global__ void __launch_bounds__(256) z_ca_kernel(float* __restrict__ Z)
{
    gemm_core<false, false>(g_S32, g_V32, Z, N_TOK, D_MOD, 1.0f);
}

// ---------------------------------------------------------------------------
// elementwise rna-round to tf32 bit pattern
// ---------------------------------------------------------------------------
__global__ void cvt_kernel(const float4* __restrict__ in, float4* __restrict__ out, int n4)
{
    int i = blockIdx.x * blockDim.x + threadIdx.x;
    if (i >= n4) return;
    float4 v = in[i];
    float4 o;
    o.x = __uint_as_float(f2tf32(v.x));
    o.y = __uint_as_float(f2tf32(v.y));
    o.z = __uint_as_float(f2tf32(v.z));
    o.w = __uint_as_float(f2tf32(v.w));
    out[i] = o;
}

// ---------------------------------------------------------------------------
// sigma[i] = clip(x[i,:].Ws, 0.001, 1.0) — one warp per row
// ---------------------------------------------------------------------------
__global__ void sigma_kernel(const float* __restrict__ x, const float* __restrict__ Ws)
{
    int row  = blockIdx.x * (blockDim.x >> 5) + (threadIdx.x >> 5);
    int lane = threadIdx.x & 31;
    if (row >= N_TOK) return;
    const float4* xr = (const float4*)(x + (size_t)row * D_MOD);
    const float4* w  = (const float4*)Ws;
    float s = 0.f;
#pragma unroll
    for (int k = lane; k < D_MOD / 4; k += 32) {
        float4 a = xr[k], b = w[k];
        s += a.x * b.x + a.y * b.y + a.z * b.z + a.w * b.w;
    }
#pragma unroll
    for (int o = 16; o; o >>= 1) s += __shfl_xor_sync(0xffffffffu, s, o);
    if (lane == 0) g_sigma[row] = fminf(fmaxf(s, 0.001f), 1.0f);
}

// ---------------------------------------------------------------------------
// P row kernel: zero the whole row, then Gaussian band (fp32 underflow makes
// exp term exactly 0 for |i-j| >= 15 since sigma <= 1). One block per row.
// ---------------------------------------------------------------------------
#define BAND 32

__global__ void p_row_kernel(float* __restrict__ P)
{
    const int row = blockIdx.x;
    const int t = threadIdx.x;
    float4* prow4 = (float4*)(P + (size_t)row * N_TOK);
#pragma unroll
    for (int j = t; j < N_TOK / 4; j += 256)
        prow4[j] = make_float4(0.f, 0.f, 0.f, 0.f);
    __syncthreads();

    if (t < 32) {
        const int lane = t;
        const float sg  = g_sigma[row];
        const float inv = 1.0f / sg;
        const float cc  = rsqrtf(6.283185307179586f * sg);
        const int j0 = max(row - BAND, 0);
        const int j1 = min(row + BAND, N_TOK - 1);

        float sum = 0.f;
        for (int j = j0 + lane; j <= j1; j += 32) {
            float u = (float)(j - row) * inv;
            sum += cc * __expf(-0.5f * u * u);
        }
#pragma unroll
        for (int o = 16; o; o >>= 1) sum += __shfl_xor_sync(0xffffffffu, sum, o);
        const float scale = 1.0f / (sum + 1e-8f);

        for (int j = j0 + lane; j <= j1; j += 32) {
            float u = (float)(j - row) * inv;
            P[(size_t)row * N_TOK + j] = cc * __expf(-0.5f * u * u) * scale;
        }
    }
}

// ---------------------------------------------------------------------------
// in-place row softmax; also writes tf32-rounded copy for the Z GEMM
// ---------------------------------------------------------------------------
__global__ void softmax_kernel(float* __restrict__ S, float* __restrict__ S32)
{
    __shared__ float buf[N_TOK];
    __shared__ float red[8];
    const int row = blockIdx.x;
    const int t = threadIdx.x;
    const int lane = t & 31, w = t >> 5;
    float* srow   = S   + (size_t)row * N_TOK;
    float* srow32 = S32 + (size_t)row * N_TOK;

    float m = -INFINITY;
    for (int j = t; j < N_TOK; j += 256) {
        float v = srow[j];
        buf[j] = v;
        m = fmaxf(m, v);
    }
#pragma unroll
    for (int o = 16; o; o >>= 1) m = fmaxf(m, __shfl_xor_sync(0xffffffffu, m, o));
    if (lane == 0) red[w] = m;
    __syncthreads();
    if (t == 0) {
        float v = red[0];
#pragma unroll
        for (int i = 1; i < 8; i++) v = fmaxf(v, red[i]);
        red[0] = v;
    }
    __syncthreads();
    m = red[0];
    __syncthreads();

    float sum = 0.f;
    for (int j = t; j < N_TOK; j += 256) {
        float e = __expf(buf[j] - m);
        buf[j] = e;
        sum += e;
    }
#pragma unroll
    for (int o = 16; o; o >>= 1) sum += __shfl_xor_sync(0xffffffffu, sum, o);
    if (lane == 0) red[w] = sum;
    __syncthreads();
    if (t == 0) {
        float s = 0.f;
#pragma unroll
        for (int i = 0; i < 8; i++) s += red[i];
        red[0] = s;
    }
    __syncthreads();
    const float scale = 1.0f / red[0];

    for (int j = t; j < N_TOK; j += 256) {
        float v = buf[j] * scale;
        srow[j]   = v;
        srow32[j] = __uint_as_float(f2tf32(v));
    }
}

// ---------------------------------------------------------------------------
extern "C" void kernel_launch(void* const* d_in, const int* in_sizes, int n_in,
                              void* d_out, int out_size)
{
    const float* x  = (const float*)d_in[0];
    const float* Wq = (const float*)d_in[1];
    const float* Wk = (const float*)d_in[2];
    const float* Wv = (const float*)d_in[3];
    const float* Ws = (const float*)d_in[4];

    float* out = (float*)d_out;
    float* Z = out;                          // [4096, 512]
    float* P = out + (size_t)N_TOK * D_MOD;  // [4096, 4096]
    float* S = P + (size_t)N_TOK * N_TOK;    // [4096, 4096]

    cudaFuncSetAttribute(qkv_ca_kernel, cudaFuncAttributeMaxDynamicSharedMemorySize, DYN_SMEM);
    cudaFuncSetAttribute(s_ca_kernel,   cudaFuncAttributeMaxDynamicSharedMemorySize, DYN_SMEM);
    cudaFuncSetAttribute(z_ca_kernel,   cudaFuncAttributeMaxDynamicSharedMemorySize, DYN_SMEM);

    float *x32p, *wq32p, *wk32p, *wv32p, *s32p;
    cudaGetSymbolAddress((void**)&x32p,  g_X32);
    cudaGetSymbolAddress((void**)&wq32p, g_Wq32);
    cudaGetSymbolAddress((void**)&wk32p, g_Wk32);
    cudaGetSymbolAddress((void**)&wv32p, g_Wv32);
    cudaGetSymbolAddress((void**)&s32p,  g_S32);

    dim3 blk(256);

    // 0) pre-round inputs to tf32 bit patterns
    cvt_kernel<<<(N_TOK * D_MOD / 4 + 255) / 256, blk>>>((const float4*)x,  (float4*)x32p,  N_TOK * D_MOD / 4);
    cvt_kernel<<<(D_MOD * D_MOD / 4 + 255) / 256, blk>>>((const float4*)Wq, (float4*)wq32p, D_MOD * D_MOD / 4);
    cvt_kernel<<<(D_MOD * D_MOD / 4 + 255) / 256, blk>>>((const float4*)Wk, (float4*)wk32p, D_MOD * D_MOD / 4);
    cvt_kernel<<<(D_MOD * D_MOD / 4 + 255) / 256, blk>>>((const float4*)Wv, (float4*)wv32p, D_MOD * D_MOD / 4);

    // 1) Q, K, V = x @ W^T (tf32-rounded outputs)
    dim3 gQKV(D_MOD / 128, N_TOK / 128, 3);
    qkv_ca_kernel<<<gQKV, blk, DYN_SMEM>>>();

    // 2) sigma
    sigma_kernel<<<N_TOK / 8, blk>>>(x, Ws);

    // 3) P = zeros + Gaussian band (one block per row)
    p_row_kernel<<<N_TOK, blk>>>(P);

    // 4) raw scores: S = (Q K^T)/sqrt(d)
    dim3 gS(N_TOK / 128, N_TOK / 128);
    s_ca_kernel<<<gS, blk, DYN_SMEM>>>(S);

    // 5) softmax rows in place (+ rounded copy)
    softmax_kernel<<<N_TOK, blk>>>(S, s32p);

    // 6) Z = S @ V
    dim3 gZ(D_MOD / 128, N_TOK / 128);
    z_ca_kernel<<<gZ, blk, DYN_SMEM>>>(Z);
}

// round 5
// speedup vs baseline: 5.1371x; 1.6726x over previous
#include <cuda_runtime.h>
#include <cuda_fp16.h>
#include <math.h>
#include <stdint.h>

#define N_TOK 4096
#define D_MOD 512

// scratch (static device globals — no allocation allowed)
__device__ __half g_Xh[N_TOK * D_MOD];
__device__ __half g_Wqh[D_MOD * D_MOD];
__device__ __half g_Wkh[D_MOD * D_MOD];
__device__ __half g_Wvh[D_MOD * D_MOD];
__device__ __half g_Qh[N_TOK * D_MOD];
__device__ __half g_Kh[N_TOK * D_MOD];
__device__ __half g_Vh[N_TOK * D_MOD];
__device__ __half g_Vth[D_MOD * N_TOK];      // V^T [512][4096]
__device__ __half g_Sh[(size_t)N_TOK * N_TOK];
__device__ float  g_sigma[N_TOK];

__device__ __forceinline__ uint32_t smem_u32(const void* p) {
    uint32_t a;
    asm("{ .reg .u64 t; cvta.to.shared.u64 t, %1; cvt.u32.u64 %0, t; }" : "=r"(a) : "l"(p));
    return a;
}
__device__ __forceinline__ void mma_f16(float* d, const uint32_t* a, const uint32_t* b) {
    asm volatile(
        "mma.sync.aligned.m16n8k16.row.col.f32.f16.f16.f32 "
        "{%0,%1,%2,%3}, {%4,%5,%6,%7}, {%8,%9}, {%0,%1,%2,%3};"
        : "+f"(d[0]), "+f"(d[1]), "+f"(d[2]), "+f"(d[3])
        : "r"(a[0]), "r"(a[1]), "r"(a[2]), "r"(a[3]), "r"(b[0]), "r"(b[1]));
}
__device__ __forceinline__ void cp16(uint32_t s, const void* g) {
    asm volatile("cp.async.cg.shared.global [%0], [%1], 16;" :: "r"(s), "l"(g));
}

// ---------------------------------------------------------------------------
// cp.async 3-stage fp16 GEMM (fp32 accumulate).
//   C[M,NC] = alpha * A[M,K] * B[NC,K]^T   (both K-major row-major fp16)
//   OUT_HALF: write C as fp16 (for scratch intermediates), else fp32.
// BM=BN=128, BK=64 halves, 256 threads (8 warps 2x4), warp tile 64x32.
// ---------------------------------------------------------------------------
#define STAGES 3
#define LDA 72
#define AHALVES (128 * LDA)                   // 9216 halves
#define STAGE_BYTES (2 * AHALVES * 2)         // 36864 B
#define DYN_SMEM (STAGES * STAGE_BYTES)       // 110592 B

template <bool OUT_HALF>
__device__ __forceinline__ void gemm_fp16(
    const __half* __restrict__ A, const __half* __restrict__ B,
    void* __restrict__ Cv, int K, int NC, float alpha)
{
    extern __shared__ __half smh[];
    const uint32_t smem_base = smem_u32(smh);
    const int t    = threadIdx.x;
    const int wid  = t >> 5;
    const int lane = t & 31;
    const int r    = lane >> 2;      // groupID
    const int c    = lane & 3;       // threadID in group
    const int warpM = (wid >> 2) * 64;
    const int warpN = (wid & 3) * 32;
    const int row0 = blockIdx.y * 128;
    const int col0 = blockIdx.x * 128;
    const int iters = K >> 6;

    auto stage_load = [&](int sidx) {
        const int buf = sidx % STAGES;
        const int k0  = sidx << 6;
        const uint32_t abase = smem_base + (uint32_t)buf * STAGE_BYTES;
        const uint32_t bbase = abase + AHALVES * 2;
#pragma unroll
        for (int i = 0; i < 4; i++) {
            int l = i * 256 + t;
            int rr = l >> 3, cc = (l & 7) << 3;     // 8 halves per chunk
            cp16(abase + (uint32_t)(rr * LDA + cc) * 2,
                 &A[(size_t)(row0 + rr) * K + k0 + cc]);
            cp16(bbase + (uint32_t)(rr * LDA + cc) * 2,
                 &B[(size_t)(col0 + rr) * K + k0 + cc]);
        }
        asm volatile("cp.async.commit_group;" ::: "memory");
    };

    float acc[4][4][4] = {};

    stage_load(0);
    stage_load(1);

    for (int it = 0; it < iters; ++it) {
        const int buf = it % STAGES;
        asm volatile("cp.async.wait_group %0;" :: "n"(STAGES - 2) : "memory");
        __syncthreads();
        if (it + STAGES - 1 < iters) stage_load(it + STAGES - 1);

        const __half* As = smh + (size_t)buf * (2 * AHALVES);
        const __half* Bs = As + AHALVES;

#pragma unroll
        for (int kk = 0; kk < 64; kk += 16) {
            uint32_t af[4][4], bf[4][2];
#pragma unroll
            for (int mi = 0; mi < 4; mi++) {
                const __half* base = &As[(warpM + mi * 16 + r) * LDA + kk + 2 * c];
                af[mi][0] = *(const uint32_t*)(base);
                af[mi][1] = *(const uint32_t*)(base + 8 * LDA);
                af[mi][2] = *(const uint32_t*)(base + 8);
                af[mi][3] = *(const uint32_t*)(base + 8 * LDA + 8);
            }
#pragma unroll
            for (int ni = 0; ni < 4; ni++) {
                const __half* base = &Bs[(warpN + ni * 8 + r) * LDA + kk + 2 * c];
                bf[ni][0] = *(const uint32_t*)(base);
                bf[ni][1] = *(const uint32_t*)(base + 8);
            }
#pragma unroll
            for (int mi = 0; mi < 4; mi++)
#pragma unroll
                for (int ni = 0; ni < 4; ni++)
                    mma_f16(acc[mi][ni], af[mi], bf[ni]);
        }
    }

    // epilogue
#pragma unroll
    for (int mi = 0; mi < 4; mi++) {
        int row = row0 + warpM + mi * 16 + r;
#pragma unroll
        for (int ni = 0; ni < 4; ni++) {
            int col = col0 + warpN + ni * 8 + 2 * c;
            float o0 = alpha * acc[mi][ni][0], o1 = alpha * acc[mi][ni][1];
            float o2 = alpha * acc[mi][ni][2], o3 = alpha * acc[mi][ni][3];
            if (OUT_HALF) {
                __half* Ch = (__half*)Cv;
                *(__half2*)&Ch[(size_t)row * NC + col]       = __floats2half2_rn(o0, o1);
                *(__half2*)&Ch[(size_t)(row + 8) * NC + col] = __floats2half2_rn(o2, o3);
            } else {
                float* Cf = (float*)Cv;
                *(float2*)&Cf[(size_t)row * NC + col]       = make_float2(o0, o1);
                *(float2*)&Cf[(size_t)(row + 8) * NC + col] = make_float2(o2, o3);
            }
        }
    }
}

__global__ void __launch_bounds__(256) qkv_h_kernel()
{
    if (blockIdx.z == 0)      gemm_fp16<true>(g_Xh, g_Wqh, g_Qh, D_MOD, D_MOD, 1.0f);
    else if (blockIdx.z == 1) gemm_fp16<true>(g_Xh, g_Wkh, g_Kh, D_MOD, D_MOD, 1.0f);
    else                      gemm_fp16<true>(g_Xh, g_Wvh, g_Vh, D_MOD, D_MOD, 1.0f);
}

__global__ void __launch_bounds__(256) s_h_kernel(float* __restrict__ S)
{
    gemm_fp16<false>(g_Qh, g_Kh, S, D_MOD, N_TOK, 0.044194173824159216f); // 1/sqrt(512)
}

__global__ void __launch_bounds__(256) z_h_kernel(float* __restrict__ Z)
{
    gemm_fp16<false>(g_Sh, g_Vth, Z, N_TOK, D_MOD, 1.0f);
}

// ---------------------------------------------------------------------------
// fp32 -> fp16 convert
// ---------------------------------------------------------------------------
__global__ void cvt_h_kernel(const float4* __restrict__ in, __half* __restrict__ out, int n4)
{
    int i = blockIdx.x * blockDim.x + threadIdx.x;
    if (i >= n4) return;
    float4 v = in[i];
    __half2 h0 = __floats2half2_rn(v.x, v.y);
    __half2 h1 = __floats2half2_rn(v.z, v.w);
    *(__half2*)&out[i * 4]     = h0;
    *(__half2*)&out[i * 4 + 2] = h1;
}

// ---------------------------------------------------------------------------
// transpose g_Vh [4096][512] -> g_Vth [512][4096]
// ---------------------------------------------------------------------------
__global__ void transpose_v_kernel()
{
    __shared__ __half tile[32][33];
    const int c0 = blockIdx.x * 32;   // col in Vh
    const int r0 = blockIdx.y * 32;   // row in Vh
    const int tx = threadIdx.x & 31;
    const int ty = threadIdx.x >> 5;  // 0..7
#pragma unroll
    for (int i = 0; i < 4; i++) {
        int row = ty + i * 8;
        tile[row][tx] = g_Vh[(size_t)(r0 + row) * D_MOD + c0 + tx];
    }
    __syncthreads();
#pragma unroll
    for (int i = 0; i < 4; i++) {
        int row = ty + i * 8;
        g_Vth[(size_t)(c0 + row) * N_TOK + r0 + tx] = tile[tx][row];
    }
}

// ---------------------------------------------------------------------------
// sigma[i] = clip(x[i,:].Ws, 0.001, 1.0) — one warp per row (fp32 inputs)
// ---------------------------------------------------------------------------
__global__ void sigma_kernel(const float* __restrict__ x, const float* __restrict__ Ws)
{
    int row  = blockIdx.x * (blockDim.x >> 5) + (threadIdx.x >> 5);
    int lane = threadIdx.x & 31;
    if (row >= N_TOK) return;
    const float4* xr = (const float4*)(x + (size_t)row * D_MOD);
    const float4* w  = (const float4*)Ws;
    float s = 0.f;
#pragma unroll
    for (int k = lane; k < D_MOD / 4; k += 32) {
        float4 a = xr[k], b = w[k];
        s += a.x * b.x + a.y * b.y + a.z * b.z + a.w * b.w;
    }
#pragma unroll
    for (int o = 16; o; o >>= 1) s += __shfl_xor_sync(0xffffffffu, s, o);
    if (lane == 0) g_sigma[row] = fminf(fmaxf(s, 0.001f), 1.0f);
}

// ---------------------------------------------------------------------------
// P row kernel: zero the row, then Gaussian band (fp32 underflow makes the
// exp term exactly 0 for |i-j| >= 15 since sigma <= 1). One block per row.
// ---------------------------------------------------------------------------
#define BAND 32

__global__ void p_row_kernel(float* __restrict__ P)
{
    const int row = blockIdx.x;
    const int t = threadIdx.x;
    float4* prow4 = (float4*)(P + (size_t)row * N_TOK);
#pragma unroll
    for (int j = t; j < N_TOK / 4; j += 256)
        prow4[j] = make_float4(0.f, 0.f, 0.f, 0.f);
    __syncthreads();

    if (t < 32) {
        const int lane = t;
        const float sg  = g_sigma[row];
        const float inv = 1.0f / sg;
        const float cc  = rsqrtf(6.283185307179586f * sg);
        const int j0 = max(row - BAND, 0);
        const int j1 = min(row + BAND, N_TOK - 1);

        float sum = 0.f;
        for (int j = j0 + lane; j <= j1; j += 32) {
            float u = (float)(j - row) * inv;
            sum += cc * __expf(-0.5f * u * u);
        }
#pragma unroll
        for (int o = 16; o; o >>= 1) sum += __shfl_xor_sync(0xffffffffu, sum, o);
        const float scale = 1.0f / (sum + 1e-8f);

        for (int j = j0 + lane; j <= j1; j += 32) {
            float u = (float)(j - row) * inv;
            P[(size_t)row * N_TOK + j] = cc * __expf(-0.5f * u * u) * scale;
        }
    }
}

// ---------------------------------------------------------------------------
// in-place row softmax on S; also writes fp16 copy for the Z GEMM
// ---------------------------------------------------------------------------
__global__ void softmax_kernel(float* __restrict__ S, __half* __restrict__ Sh)
{
    __shared__ float buf[N_TOK];
    __shared__ float red[8];
    const int row = blockIdx.x;
    const int t = threadIdx.x;
    const int lane = t & 31, w = t >> 5;
    float*  srow  = S  + (size_t)row * N_TOK;
    __half* srowh = Sh + (size_t)row * N_TOK;

    float m = -INFINITY;
    for (int j = t; j < N_TOK; j += 256) {
        float v = srow[j];
        buf[j] = v;
        m = fmaxf(m, v);
    }
#pragma unroll
    for (int o = 16; o; o >>= 1) m = fmaxf(m, __shfl_xor_sync(0xffffffffu, m, o));
    if (lane == 0) red[w] = m;
    __syncthreads();
    if (t == 0) {
        float v = red[0];
#pragma unroll
        for (int i = 1; i < 8; i++) v = fmaxf(v, red[i]);
        red[0] = v;
    }
    __syncthreads();
    m = red[0];
    __syncthreads();

    float sum = 0.f;
    for (int j = t; j < N_TOK; j += 256) {
        float e = __expf(buf[j] - m);
        buf[j] = e;
        sum += e;
    }
#pragma unroll
    for (int o = 16; o; o >>= 1) sum += __shfl_xor_sync(0xffffffffu, sum, o);
    if (lane == 0) red[w] = sum;
    __syncthreads();
    if (t == 0) {
        float s = 0.f;
#pragma unroll
        for (int i = 0; i < 8; i++) s += red[i];
        red[0] = s;
    }
    __syncthreads();
    const float scale = 1.0f / red[0];

    for (int j = t; j < N_TOK; j += 256) {
        float v = buf[j] * scale;
        srow[j]  = v;
        srowh[j] = __float2half_rn(v);
    }
}

// ---------------------------------------------------------------------------
extern "C" void kernel_launch(void* const* d_in, const int* in_sizes, int n_in,
                              void* d_out, int out_size)
{
    const float* x  = (const float*)d_in[0];
    const float* Wq = (const float*)d_in[1];
    const float* Wk = (const float*)d_in[2];
    const float* Wv = (const float*)d_in[3];
    const float* Ws = (const float*)d_in[4];

    float* out = (float*)d_out;
    float* Z = out;                          // [4096, 512]
    float* P = out + (size_t)N_TOK * D_MOD;  // [4096, 4096]
    float* S = P + (size_t)N_TOK * N_TOK;    // [4096, 4096]

    cudaFuncSetAttribute(qkv_h_kernel, cudaFuncAttributeMaxDynamicSharedMemorySize, DYN_SMEM);
    cudaFuncSetAttribute(s_h_kernel,   cudaFuncAttributeMaxDynamicSharedMemorySize, DYN_SMEM);
    cudaFuncSetAttribute(z_h_kernel,   cudaFuncAttributeMaxDynamicSharedMemorySize, DYN_SMEM);

    __half *xh, *wqh, *wkh, *wvh, *shp;
    cudaGetSymbolAddress((void**)&xh,  g_Xh);
    cudaGetSymbolAddress((void**)&wqh, g_Wqh);
    cudaGetSymbolAddress((void**)&wkh, g_Wkh);
    cudaGetSymbolAddress((void**)&wvh, g_Wvh);
    cudaGetSymbolAddress((void**)&shp, g_Sh);

    dim3 blk(256);

    // 0) convert inputs to fp16
    cvt_h_kernel<<<(N_TOK * D_MOD / 4 + 255) / 256, blk>>>((const float4*)x,  xh,  N_TOK * D_MOD / 4);
    cvt_h_kernel<<<(D_MOD * D_MOD / 4 + 255) / 256, blk>>>((const float4*)Wq, wqh, D_MOD * D_MOD / 4);
    cvt_h_kernel<<<(D_MOD * D_MOD / 4 + 255) / 256, blk>>>((const float4*)Wk, wkh, D_MOD * D_MOD / 4);
    cvt_h_kernel<<<(D_MOD * D_MOD / 4 + 255) / 256, blk>>>((const float4*)Wv, wvh, D_MOD * D_MOD / 4);

    // 1) Q, K, V = x @ W^T  (fp16 outputs)
    dim3 gQKV(D_MOD / 128, N_TOK / 128, 3);
    qkv_h_kernel<<<gQKV, blk, DYN_SMEM>>>();

    // 1b) Vt
    transpose_v_kernel<<<dim3(D_MOD / 32, N_TOK / 32), blk>>>();

    // 2) sigma
    sigma_kernel<<<N_TOK / 8, blk>>>(x, Ws);

    // 3) P = zeros + Gaussian band
    p_row_kernel<<<N_TOK, blk>>>(P);

    // 4) raw scores: S = (Q K^T)/sqrt(d)
    dim3 gS(N_TOK / 128, N_TOK / 128);
    s_h_kernel<<<gS, blk, DYN_SMEM>>>(S);

    // 5) softmax rows in place (+ fp16 copy)
    softmax_kernel<<<N_TOK, blk>>>(S, shp);

    // 6) Z = S @ V
    dim3 gZ(D_MOD / 128, N_TOK / 128);
    z_h_kernel<<<gZ, blk, DYN_SMEM>>>(Z);
}

// round 6
// speedup vs baseline: 5.8316x; 1.1352x over previous
#include <cuda_runtime.h>
#include <cuda_fp16.h>
#include <math.h>
#include <stdint.h>

#define N_TOK 4096
#define D_MOD 512

// scratch (static device globals — no allocation allowed)
__device__ __half g_Xh[N_TOK * D_MOD];
__device__ __half g_Wqh[D_MOD * D_MOD];
__device__ __half g_Wkh[D_MOD * D_MOD];
__device__ __half g_Wvh[D_MOD * D_MOD];
__device__ __half g_Qh[N_TOK * D_MOD];
__device__ __half g_Kh[N_TOK * D_MOD];
__device__ __half g_Vh[N_TOK * D_MOD];
__device__ __half g_Vth[D_MOD * N_TOK];      // V^T [512][4096]
__device__ __half g_Sh[(size_t)N_TOK * N_TOK];
__device__ float  g_sigma[N_TOK];

__device__ __forceinline__ uint32_t smem_u32(const void* p) {
    uint32_t a;
    asm("{ .reg .u64 t; cvta.to.shared.u64 t, %1; cvt.u32.u64 %0, t; }" : "=r"(a) : "l"(p));
    return a;
}
__device__ __forceinline__ void mma_f16(float* d, const uint32_t* a, const uint32_t* b) {
    asm volatile(
        "mma.sync.aligned.m16n8k16.row.col.f32.f16.f16.f32 "
        "{%0,%1,%2,%3}, {%4,%5,%6,%7}, {%8,%9}, {%0,%1,%2,%3};"
        : "+f"(d[0]), "+f"(d[1]), "+f"(d[2]), "+f"(d[3])
        : "r"(a[0]), "r"(a[1]), "r"(a[2]), "r"(a[3]), "r"(b[0]), "r"(b[1]));
}
__device__ __forceinline__ void ldsm4(uint32_t* r, uint32_t addr) {
    asm volatile("ldmatrix.sync.aligned.m8n8.x4.shared.b16 {%0,%1,%2,%3}, [%4];"
        : "=r"(r[0]), "=r"(r[1]), "=r"(r[2]), "=r"(r[3]) : "r"(addr));
}
__device__ __forceinline__ void cp16(uint32_t s, const void* g) {
    asm volatile("cp.async.cg.shared.global [%0], [%1], 16;" :: "r"(s), "l"(g));
}

// ---------------------------------------------------------------------------
// cp.async 4-stage fp16 GEMM (fp32 accumulate), ldmatrix fragment loads.
//   C[M,NC] = alpha * A[M,K] * B[NC,K]^T   (both K-major row-major fp16)
// Tile layout in smem: 128 rows x 8 chunks of 16B (64 halves per row),
// XOR swizzle: physical chunk = c ^ (row & 7). Conflict-free for cp.async
// 16B stores and for ldmatrix 8-row gathers.
// BM=BN=128, BK=64 halves, 256 threads (8 warps 2x4), warp tile 64x32.
// ---------------------------------------------------------------------------
#define STAGES 4
#define TILE_BYTES 16384                      // 128 rows * 128B
#define STAGE_BYTES (2 * TILE_BYTES)          // A + B = 32 KB
#define DYN_SMEM (STAGES * STAGE_BYTES)       // 128 KB

template <bool OUT_HALF>
__device__ __forceinline__ void gemm_fp16(
    const __half* __restrict__ A, const __half* __restrict__ B,
    void* __restrict__ Cv, int K, int NC, float alpha)
{
    extern __shared__ __half smh[];
    const uint32_t smem_base = smem_u32(smh);
    const int t    = threadIdx.x;
    const int wid  = t >> 5;
    const int lane = t & 31;
    const int r    = lane >> 2;
    const int c    = lane & 3;
    const int warpM = (wid >> 2) * 64;
    const int warpN = (wid & 3) * 32;
    const int row0 = blockIdx.y * 128;
    const int col0 = blockIdx.x * 128;
    const int iters = K >> 6;

    auto stage_load = [&](int sidx) {
        const int buf = sidx & (STAGES - 1);
        const int k0  = sidx << 6;
        const uint32_t abase = smem_base + (uint32_t)buf * STAGE_BYTES;
        const uint32_t bbase = abase + TILE_BYTES;
#pragma unroll
        for (int i = 0; i < 4; i++) {
            int lc = i * 256 + t;             // 0..1023 chunk id
            int rr = lc >> 3, cc = lc & 7;
            uint32_t so = (uint32_t)((rr << 3) + (cc ^ (rr & 7))) << 4;
            cp16(abase + so, &A[(size_t)(row0 + rr) * K + k0 + (cc << 3)]);
            cp16(bbase + so, &B[(size_t)(col0 + rr) * K + k0 + (cc << 3)]);
        }
        asm volatile("cp.async.commit_group;" ::: "memory");
    };

    // per-thread ldmatrix row/chunk components (constant across kk)
    const int a_row_lo = lane & 15;           // within 16-row tile
    const int a_chi    = lane >> 4;           // 0/1 -> +chunk
    const int b_row_lo = (lane & 7) + ((lane >> 4) << 3);  // m0/m1: +0..7, m2/m3: +8..15
    const int b_chi    = (lane >> 3) & 1;

    float acc[4][4][4] = {};

    stage_load(0);
    stage_load(1);
    stage_load(2);

    for (int it = 0; it < iters; ++it) {
        const int buf = it & (STAGES - 1);
        asm volatile("cp.async.wait_group %0;" :: "n"(STAGES - 2) : "memory");
        __syncthreads();
        if (it + STAGES - 1 < iters) stage_load(it + STAGES - 1);

        const uint32_t abase = smem_base + (uint32_t)buf * STAGE_BYTES;
        const uint32_t bbase = abase + TILE_BYTES;

#pragma unroll
        for (int kk4 = 0; kk4 < 4; kk4++) {   // k-chunk pair
            const int ca = kk4 * 2 + a_chi;
            const int cb = kk4 * 2 + b_chi;
            uint32_t af[4][4], bq[2][4];
#pragma unroll
            for (int mi = 0; mi < 4; mi++) {
                int row = warpM + mi * 16 + a_row_lo;
                uint32_t addr = abase + ((uint32_t)((row << 3) + (ca ^ (row & 7))) << 4);
                ldsm4(af[mi], addr);
            }
#pragma unroll
            for (int np = 0; np < 2; np++) {
                int row = warpN + np * 16 + b_row_lo;
                uint32_t addr = bbase + ((uint32_t)((row << 3) + (cb ^ (row & 7))) << 4);
                ldsm4(bq[np], addr);
            }
#pragma unroll
            for (int mi = 0; mi < 4; mi++)
#pragma unroll
                for (int ni = 0; ni < 4; ni++)
                    mma_f16(acc[mi][ni], af[mi], &bq[ni >> 1][(ni & 1) * 2]);
        }
    }

    // epilogue
#pragma unroll
    for (int mi = 0; mi < 4; mi++) {
        int row = row0 + warpM + mi * 16 + r;
#pragma unroll
        for (int ni = 0; ni < 4; ni++) {
            int col = col0 + warpN + ni * 8 + 2 * c;
            float o0 = alpha * acc[mi][ni][0], o1 = alpha * acc[mi][ni][1];
            float o2 = alpha * acc[mi][ni][2], o3 = alpha * acc[mi][ni][3];
            if (OUT_HALF) {
                __half* Ch = (__half*)Cv;
                *(__half2*)&Ch[(size_t)row * NC + col]       = __floats2half2_rn(o0, o1);
                *(__half2*)&Ch[(size_t)(row + 8) * NC + col] = __floats2half2_rn(o2, o3);
            } else {
                float* Cf = (float*)Cv;
                *(float2*)&Cf[(size_t)row * NC + col]       = make_float2(o0, o1);
                *(float2*)&Cf[(size_t)(row + 8) * NC + col] = make_float2(o2, o3);
            }
        }
    }
}

__global__ void __launch_bounds__(256) qkv_h_kernel()
{
    if (blockIdx.z == 0)      gemm_fp16<true>(g_Xh, g_Wqh, g_Qh, D_MOD, D_MOD, 1.0f);
    else if (blockIdx.z == 1) gemm_fp16<true>(g_Xh, g_Wkh, g_Kh, D_MOD, D_MOD, 1.0f);
    else                      gemm_fp16<true>(g_Xh, g_Wvh, g_Vh, D_MOD, D_MOD, 1.0f);
}

__global__ void __launch_bounds__(256) s_h_kernel(float* __restrict__ S)
{
    gemm_fp16<false>(g_Qh, g_Kh, S, D_MOD, N_TOK, 0.044194173824159216f); // 1/sqrt(512)
}

__global__ void __launch_bounds__(256) z_h_kernel(float* __restrict__ Z)
{
    gemm_fp16<false>(g_Sh, g_Vth, Z, N_TOK, D_MOD, 1.0f);
}

// ---------------------------------------------------------------------------
// fused fp32 -> fp16 convert for x, Wq, Wk, Wv (one launch)
// ---------------------------------------------------------------------------
#define X4   (N_TOK * D_MOD / 4)    // 524288 floats -> 131072 float4
#define W4   (D_MOD * D_MOD / 4)    // 65536 float4 each

__global__ void cvt_all_kernel(const float4* __restrict__ x,
                               const float4* __restrict__ Wq,
                               const float4* __restrict__ Wk,
                               const float4* __restrict__ Wv)
{
    int i = blockIdx.x * blockDim.x + threadIdx.x;
    const float4* in;
    __half* out;
    int idx;
    if (i < X4)                { in = x;  out = g_Xh;  idx = i; }
    else if (i < X4 + W4)      { in = Wq; out = g_Wqh; idx = i - X4; }
    else if (i < X4 + 2 * W4)  { in = Wk; out = g_Wkh; idx = i - X4 - W4; }
    else if (i < X4 + 3 * W4)  { in = Wv; out = g_Wvh; idx = i - X4 - 2 * W4; }
    else return;
    float4 v = in[idx];
    *(__half2*)&out[idx * 4]     = __floats2half2_rn(v.x, v.y);
    *(__half2*)&out[idx * 4 + 2] = __floats2half2_rn(v.z, v.w);
}

// ---------------------------------------------------------------------------
// transpose g_Vh [4096][512] -> g_Vth [512][4096]
// ---------------------------------------------------------------------------
__global__ void transpose_v_kernel()
{
    __shared__ __half tile[32][33];
    const int c0 = blockIdx.x * 32;
    const int r0 = blockIdx.y * 32;
    const int tx = threadIdx.x & 31;
    const int ty = threadIdx.x >> 5;
#pragma unroll
    for (int i = 0; i < 4; i++) {
        int row = ty + i * 8;
        tile[row][tx] = g_Vh[(size_t)(r0 + row) * D_MOD + c0 + tx];
    }
    __syncthreads();
#pragma unroll
    for (int i = 0; i < 4; i++) {
        int row = ty + i * 8;
        g_Vth[(size_t)(c0 + row) * N_TOK + r0 + tx] = tile[tx][row];
    }
}

// ---------------------------------------------------------------------------
// sigma[i] = clip(x[i,:].Ws, 0.001, 1.0) — one warp per row (fp32 inputs)
// ---------------------------------------------------------------------------
__global__ void sigma_kernel(const float* __restrict__ x, const float* __restrict__ Ws)
{
    int row  = blockIdx.x * (blockDim.x >> 5) + (threadIdx.x >> 5);
    int lane = threadIdx.x & 31;
    if (row >= N_TOK) return;
    const float4* xr = (const float4*)(x + (size_t)row * D_MOD);
    const float4* w  = (const float4*)Ws;
    float s = 0.f;
#pragma unroll
    for (int k = lane; k < D_MOD / 4; k += 32) {
        float4 a = xr[k], b = w[k];
        s += a.x * b.x + a.y * b.y + a.z * b.z + a.w * b.w;
    }
#pragma unroll
    for (int o = 16; o; o >>= 1) s += __shfl_xor_sync(0xffffffffu, s, o);
    if (lane == 0) g_sigma[row] = fminf(fmaxf(s, 0.001f), 1.0f);
}

// ---------------------------------------------------------------------------
// P row kernel: zero the row, then Gaussian band (fp32 underflow makes the
// exp term exactly 0 for |i-j| >= 15 since sigma <= 1). One block per row.
// ---------------------------------------------------------------------------
#define BAND 32

__global__ void p_row_kernel(float* __restrict__ P)
{
    const int row = blockIdx.x;
    const int t = threadIdx.x;
    float4* prow4 = (float4*)(P + (size_t)row * N_TOK);
#pragma unroll
    for (int j = t; j < N_TOK / 4; j += 256)
        prow4[j] = make_float4(0.f, 0.f, 0.f, 0.f);
    __syncthreads();

    if (t < 32) {
        const int lane = t;
        const float sg  = g_sigma[row];
        const float inv = 1.0f / sg;
        const float cc  = rsqrtf(6.283185307179586f * sg);
        const int j0 = max(row - BAND, 0);
        const int j1 = min(row + BAND, N_TOK - 1);

        float sum = 0.f;
        for (int j = j0 + lane; j <= j1; j += 32) {
            float u = (float)(j - row) * inv;
            sum += cc * __expf(-0.5f * u * u);
        }
#pragma unroll
        for (int o = 16; o; o >>= 1) sum += __shfl_xor_sync(0xffffffffu, sum, o);
        const float scale = 1.0f / (sum + 1e-8f);

        for (int j = j0 + lane; j <= j1; j += 32) {
            float u = (float)(j - row) * inv;
            P[(size_t)row * N_TOK + j] = cc * __expf(-0.5f * u * u) * scale;
        }
    }
}

// ---------------------------------------------------------------------------
// in-place row softmax on S; also writes fp16 copy for the Z GEMM
// ---------------------------------------------------------------------------
__global__ void softmax_kernel(float* __restrict__ S, __half* __restrict__ Sh)
{
    __shared__ float buf[N_TOK];
    __shared__ float red[8];
    const int row = blockIdx.x;
    const int t = threadIdx.x;
    const int lane = t & 31, w = t >> 5;
    float*  srow  = S  + (size_t)row * N_TOK;
    __half* srowh = Sh + (size_t)row * N_TOK;

    float m = -INFINITY;
    for (int j = t; j < N_TOK; j += 256) {
        float v = srow[j];
        buf[j] = v;
        m = fmaxf(m, v);
    }
#pragma unroll
    for (int o = 16; o; o >>= 1) m = fmaxf(m, __shfl_xor_sync(0xffffffffu, m, o));
    if (lane == 0) red[w] = m;
    __syncthreads();
    if (t == 0) {
        float v = red[0];
#pragma unroll
        for (int i = 1; i < 8; i++) v = fmaxf(v, red[i]);
        red[0] = v;
    }
    __syncthreads();
    m = red[0];
    __syncthreads();

    float sum = 0.f;
    for (int j = t; j < N_TOK; j += 256) {
        float e = __expf(buf[j] - m);
        buf[j] = e;
        sum += e;
    }
#pragma unroll
    for (int o = 16; o; o >>= 1) sum += __shfl_xor_sync(0xffffffffu, sum, o);
    if (lane == 0) red[w] = sum;
    __syncthreads();
    if (t == 0) {
        float s = 0.f;
#pragma unroll
        for (int i = 0; i < 8; i++) s += red[i];
        red[0] = s;
    }
    __syncthreads();
    const float scale = 1.0f / red[0];

    for (int j = t; j < N_TOK; j += 256) {
        float v = buf[j] * scale;
        srow[j]  = v;
        srowh[j] = __float2half_rn(v);
    }
}

// ---------------------------------------------------------------------------
extern "C" void kernel_launch(void* const* d_in, const int* in_sizes, int n_in,
                              void* d_out, int out_size)
{
    const float* x  = (const float*)d_in[0];
    const float* Wq = (const float*)d_in[1];
    const float* Wk = (const float*)d_in[2];
    const float* Wv = (const float*)d_in[3];
    const float* Ws = (const float*)d_in[4];

    float* out = (float*)d_out;
    float* Z = out;                          // [4096, 512]
    float* P = out + (size_t)N_TOK * D_MOD;  // [4096, 4096]
    float* S = P + (size_t)N_TOK * N_TOK;    // [4096, 4096]

    cudaFuncSetAttribute(qkv_h_kernel, cudaFuncAttributeMaxDynamicSharedMemorySize, DYN_SMEM);
    cudaFuncSetAttribute(s_h_kernel,   cudaFuncAttributeMaxDynamicSharedMemorySize, DYN_SMEM);
    cudaFuncSetAttribute(z_h_kernel,   cudaFuncAttributeMaxDynamicSharedMemorySize, DYN_SMEM);

    __half* shp;
    cudaGetSymbolAddress((void**)&shp, g_Sh);

    dim3 blk(256);

    // 0) convert inputs to fp16 (one fused launch)
    cvt_all_kernel<<<(X4 + 3 * W4 + 255) / 256, blk>>>(
        (const float4*)x, (const float4*)Wq, (const float4*)Wk, (const float4*)Wv);

    // 1) Q, K, V = x @ W^T  (fp16 outputs)
    dim3 gQKV(D_MOD / 128, N_TOK / 128, 3);
    qkv_h_kernel<<<gQKV, blk, DYN_SMEM>>>();

    // 1b) Vt
    transpose_v_kernel<<<dim3(D_MOD / 32, N_TOK / 32), blk>>>();

    // 2) sigma
    sigma_kernel<<<N_TOK / 8, blk>>>(x, Ws);

    // 3) P = zeros + Gaussian band
    p_row_kernel<<<N_TOK, blk>>>(P);

    // 4) raw scores: S = (Q K^T)/sqrt(d)
    dim3 gS(N_TOK / 128, N_TOK / 128);
    s_h_kernel<<<gS, blk, DYN_SMEM>>>(S);

    // 5) softmax rows in place (+ fp16 copy)
    softmax_kernel<<<N_TOK, blk>>>(S, shp);

    // 6) Z = S @ V
    dim3 gZ(D_MOD / 128, N_TOK / 128);
    z_h_kernel<<<gZ, blk, DYN_SMEM>>>(Z);
}